// round 16
// baseline (speedup 1.0000x reference)
#include <cuda_runtime.h>
#include <math.h>

#define B 4
#define N 512
#define HID 100
#define HP 128
#define OUTF 6
#define FULL 0xFFFFFFFFu
#define NT 256               // threads per block
#define WPB 8                // warps per block
#define WAIT_BLKS 32         // waiter blocks per batch (k < 32)

// Scratch (static device; no allocation anywhere). Device globals zero-init;
// g_S columns >= HID are never written and stay 0.0 (safe to read).
__device__ float g_S[B * N * HP];
__device__ int   g_cnt[B];
__device__ int   g_fin[B];

__device__ __forceinline__ float softplus_f(float v)
{
    return fmaxf(v, 0.f) + log1pf(expf(-fabsf(v)));
}

// ---------------------------------------------------------------------------
// One fused kernel, grid = 400 blocks x 256 threads (ALL co-resident: one
// wave).  Block (b,k): thread holds elements e0=tid, e1=tid+256.
// Phase 1: P,Q for both nodes; 512-wide bitonic sort (2 elems/thread:
//   stride 256 in-register, 32..128 via smem, <=16 via shfl); two-level
//   shuffle scan; 2 binary searches -> closed-form T -> S -> g_S.
// Release: per-batch counter (100 columns).
// Phase 2 (k < 32 only): wait for own batch, then 16 rows of the 100->6
//   GEMV epilogue (warp per row, W2 in registers) + softplus combine.
// ---------------------------------------------------------------------------
__global__ __launch_bounds__(NT) void kAB(
    const float* __restrict__ inp, const float* __restrict__ W1,
    const float* __restrict__ b1,  const float* __restrict__ W2,
    const float* __restrict__ b2,  float* __restrict__ out)
{
    int b    = blockIdx.x / HID;
    int k    = blockIdx.x - b * HID;
    int tid  = threadIdx.x;
    int lane = tid & 31;
    int wid  = tid >> 5;

    __shared__ float Qs[N];
    __shared__ float Cs[N];
    __shared__ float x0[NT], x1[NT];
    __shared__ float w0s[WPB], w1s[WPB];

    // features for this thread's two nodes
    const float* e0 = inp + (b * N + tid) * 6;
    const float* e1 = inp + (b * N + tid + 256) * 6;
    float y0 = e0[0], xx0 = e0[1], t0 = e0[2], sg0 = e0[3], c0 = e0[4], d0 = e0[5];
    float y1 = e1[0], xx1 = e1[1], t1 = e1[2], sg1 = e1[3], c1 = e1[4], d1 = e1[5];

    // W1 column k (uniform across block)
    float w0 = W1[0*HID+k], w1 = W1[1*HID+k], w2 = W1[2*HID+k], w3 = W1[3*HID+k];
    float w4 = W1[4*HID+k], w5 = W1[5*HID+k], w6 = W1[6*HID+k], w7 = W1[7*HID+k];
    float w8 = W1[8*HID+k], w9 = W1[9*HID+k], bk = b1[k];

    float P0 = t0*w0 + sg0*w1 + c0*w2 + d0*w3 + y0*w8 + xx0*w9 + bk;
    float Q0 = t0*w4 + sg0*w5 + c0*w6 + d0*w7 - y0*w8 - xx0*w9;
    float P1 = t1*w0 + sg1*w1 + c1*w2 + d1*w3 + y1*w8 + xx1*w9 + bk;
    float Q1 = t1*w4 + sg1*w5 + c1*w6 + d1*w7 - y1*w8 - xx1*w9;

    // ---- bitonic sort of 512 elements (ascending in e = tid + 256*r)
    float v0 = Q0, v1 = Q1;
    #pragma unroll 1
    for (int size = 2; size <= N; size <<= 1) {
        #pragma unroll 1
        for (int stride = size >> 1; stride > 0; stride >>= 1) {
            if (stride == 256) {             // only in size=512 stage; both asc
                float a = fminf(v0, v1), bb = fmaxf(v0, v1);
                v0 = a; v1 = bb;
                continue;
            }
            bool up0 = (size == 512) ? true : ((tid & size) == 0);
            bool up1 = (size == 512) ? true
                     : ((size == 256) ? false : ((tid & size) == 0));
            bool lower = ((tid & stride) == 0);
            float pv0, pv1;
            if (stride >= 32) {
                x0[tid] = v0; x1[tid] = v1;
                __syncthreads();
                pv0 = x0[tid ^ stride]; pv1 = x1[tid ^ stride];
                __syncthreads();
            } else {
                pv0 = __shfl_xor_sync(FULL, v0, stride);
                pv1 = __shfl_xor_sync(FULL, v1, stride);
            }
            v0 = (lower == up0) ? fminf(v0, pv0) : fmaxf(v0, pv0);
            v1 = (lower == up1) ? fminf(v1, pv1) : fmaxf(v1, pv1);
        }
    }
    // sorted: element tid = v0, element tid+256 = v1

    // ---- inclusive scan: warp shfl scans + 8-entry warp-sum combine
    float s0 = v0, s1 = v1;
    #pragma unroll
    for (int off = 1; off < 32; off <<= 1) {
        float a = __shfl_up_sync(FULL, s0, off);
        float bb = __shfl_up_sync(FULL, s1, off);
        if (lane >= off) { s0 += a; s1 += bb; }
    }
    if (lane == 31) { w0s[wid] = s0; w1s[wid] = s1; }
    __syncthreads();
    float base0 = 0.f, tot0 = 0.f, base1 = 0.f, tot1 = 0.f;
    #pragma unroll
    for (int j = 0; j < WPB; j++) {
        float a = w0s[j], bb = w1s[j];
        tot0 += a; tot1 += bb;
        if (j < wid) { base0 += a; base1 += bb; }
    }
    float SQ = tot0 + tot1;
    Qs[tid]       = v0;
    Qs[tid + 256] = v1;
    Cs[tid]       = base0 + s0;
    Cs[tid + 256] = tot0 + base1 + s1;
    __syncthreads();

    // ---- two binary searches -> S for both nodes
    #pragma unroll
    for (int r = 0; r < 2; r++) {
        float P = r ? P1 : P0;
        float Q = r ? Q1 : Q0;
        float key = -P;
        int lo = 0, hi = N;
        #pragma unroll
        for (int it = 0; it < 9; it++) {
            int mid = (lo + hi) >> 1;
            bool lt = Qs[mid] < key;
            lo = lt ? mid + 1 : lo;
            hi = lt ? hi : mid;
        }
        float Cm = (lo == 0) ? 0.f : Cs[lo - 1];
        float T  = (float)(N - 2 * lo) * P + SQ - 2.f * Cm;
        float S  = 0.55f * ((float)(N - 1) * P + SQ - Q)
                 + 0.45f * (T - fabsf(P + Q));
        g_S[(b * N + tid + r * 256) * HP + k] = S;
    }

    // ---- publish this column (release: fence all threads, then count)
    __threadfence();
    __syncthreads();
    if (tid == 0) atomicAdd(&g_cnt[b], 1);

    if (k >= WAIT_BLKS) return;

    // ---- wait for own batch (all 400 blocks co-resident: safe spin)
    if (tid == 0) {
        volatile int* cp = &g_cnt[b];
        while (*cp < HID) { __nanosleep(32); }
        __threadfence();
    }
    __syncthreads();

    // ---- epilogue: 16 rows for this block, warp per row (2 rows/warp)
    float w2r[4][OUTF];
    #pragma unroll
    for (int cc = 0; cc < 4; cc++) {
        int kc = lane + 32 * cc;
        #pragma unroll
        for (int o = 0; o < OUTF; o++)
            w2r[cc][o] = (kc < HID) ? W2[kc * OUTF + o] : 0.f;
    }

    #pragma unroll
    for (int r = 0; r < 2; r++) {
        int row = b * N + k * 16 + wid * 2 + r;     // b*N + i
        const float* Sr = g_S + row * HP;

        float par[OUTF];
        #pragma unroll
        for (int o = 0; o < OUTF; o++) par[o] = 0.f;

        #pragma unroll
        for (int cc = 0; cc < 4; cc++) {
            int kc = lane + 32 * cc;
            float sv = Sr[kc];                      // cols >= HID are 0.0
            #pragma unroll
            for (int o = 0; o < OUTF; o++)
                par[o] += sv * w2r[cc][o];
        }
        #pragma unroll
        for (int off = 16; off > 0; off >>= 1)
            #pragma unroll
            for (int o = 0; o < OUTF; o++)
                par[o] += __shfl_down_sync(FULL, par[o], off);

        if (lane == 0) {
            const float* ei = inp + row * 6;
            float* ot = out + row * 6;
            float p0 = par[0] + (float)(N - 1) * b2[0];
            float p1 = par[1] + (float)(N - 1) * b2[1];
            float p2 = par[2] + (float)(N - 1) * b2[2];
            float p3 = par[3] + (float)(N - 1) * b2[3];
            float p4 = par[4] + (float)(N - 1) * b2[4];
            float p5 = par[5] + (float)(N - 1) * b2[5];
            ot[0] = ei[0] + 0.1f * p0;
            ot[1] = ei[1] + 0.1f * p1;
            ot[2] = ei[2] + 0.1f * p2;
            ot[3] = ei[3] + 0.1f * p3;
            ot[4] = 0.1f * softplus_f(p4);
            ot[5] = 0.1f * softplus_f(p5);
        }
    }

    // ---- self-reset per-batch counters for next (graph-replayed) launch
    __syncthreads();
    if (tid == 0) {
        int old = atomicAdd(&g_fin[b], 1);
        if (old == WAIT_BLKS - 1) {
            g_cnt[b] = 0;
            g_fin[b] = 0;
            __threadfence();
        }
    }
}

// ---------------------------------------------------------------------------
extern "C" void kernel_launch(void* const* d_in, const int* in_sizes, int n_in,
                              void* d_out, int out_size)
{
    const float* inp = (const float*)d_in[0];
    const float* W1  = (const float*)d_in[1];
    const float* b1  = (const float*)d_in[2];
    const float* W2  = (const float*)d_in[3];
    const float* b2  = (const float*)d_in[4];
    float* out = (float*)d_out;

    kAB<<<B * HID, NT>>>(inp, W1, b1, W2, b2, out);
}

// round 17
// speedup vs baseline: 1.4276x; 1.4276x over previous
#include <cuda_runtime.h>
#include <math.h>

#define B 4
#define N 512
#define HID 100
#define HP 128
#define OUTF 6
#define FULL 0xFFFFFFFFu

// Scratch (static device; no allocation anywhere)
__device__ float g_S[B * N * HP];

__device__ __forceinline__ float softplus_f(float v)
{
    return fmaxf(v, 0.f) + log1pf(expf(-fabsf(v)));
}

// ---------------------------------------------------------------------------
// kA: one block per (b, k) column, 512 threads (thread = node j).
// P,Q from inp row + W1 column; hybrid bitonic sort (shfl for stride<32,
// ping-pong smem for stride>=32 -> ONE sync per pass); warp-shuffle scan;
// binary search -> closed-form T -> S_j[k].
// ---------------------------------------------------------------------------
__global__ __launch_bounds__(512) void kA(
    const float* __restrict__ inp, const float* __restrict__ W1,
    const float* __restrict__ b1)
{
    int b    = blockIdx.x / HID;
    int k    = blockIdx.x - b * HID;
    int tid  = threadIdx.x;
    int lane = tid & 31;
    int wid  = tid >> 5;

    __shared__ float Qs[N];      // sorted Q values
    __shared__ float Cs[N];      // inclusive prefix of sorted Q
    __shared__ float wsum[16];   // warp sums for scan
    __shared__ float xa[N], xb[N];  // ping-pong exchange buffers

    // node features (direct LDG; L2-resident across 400 blocks)
    const float* e = inp + (b * N + tid) * 6;
    float y = e[0], x = e[1], tau = e[2], sig = e[3], c = e[4], d = e[5];

    // W1 column k (uniform across block)
    float w0 = W1[0*HID+k], w1 = W1[1*HID+k], w2 = W1[2*HID+k], w3 = W1[3*HID+k];
    float w4 = W1[4*HID+k], w5 = W1[5*HID+k], w6 = W1[6*HID+k], w7 = W1[7*HID+k];
    float w8 = W1[8*HID+k], w9 = W1[9*HID+k], bk = b1[k];

    float P = tau*w0 + sig*w1 + c*w2 + d*w3 + y*w8 + x*w9 + bk;
    float Q = tau*w4 + sig*w5 + c*w6 + d*w7 - y*w8 - x*w9;

    // ---- bitonic sort (ascending across tid), value in register.
    // smem passes ping-pong xa/xb: single __syncthreads per pass (reuse of a
    // buffer two passes later is ordered by the intervening barrier + the
    // read->compute->write dependency).
    float v = Q;
    int flip = 0;
    #pragma unroll
    for (int size = 2; size <= N; size <<= 1) {
        bool dirAsc = ((tid & size) == 0);
        #pragma unroll
        for (int stride = size >> 1; stride > 0; stride >>= 1) {
            float pv;
            if (stride >= 32) {
                float* buf = flip ? xb : xa;
                buf[tid] = v;
                __syncthreads();
                pv = buf[tid ^ stride];
                flip ^= 1;
            } else {
                pv = __shfl_xor_sync(FULL, v, stride);
            }
            bool lower = ((tid & stride) == 0);
            v = (lower == dirAsc) ? fminf(v, pv) : fmaxf(v, pv);
        }
    }
    __syncthreads();             // last smem pass reads complete before Qs
    Qs[tid] = v;

    // ---- inclusive scan: warp shfl scan + warp-sum scan
    float s = v;
    #pragma unroll
    for (int off = 1; off < 32; off <<= 1) {
        float t = __shfl_up_sync(FULL, s, off);
        if (lane >= off) s += t;
    }
    if (lane == 31) wsum[wid] = s;
    __syncthreads();
    if (wid == 0) {
        float ws = (lane < 16) ? wsum[lane] : 0.f;
        #pragma unroll
        for (int off = 1; off < 16; off <<= 1) {
            float t = __shfl_up_sync(FULL, ws, off);
            if (lane >= off) ws += t;
        }
        if (lane < 16) wsum[lane] = ws;
    }
    __syncthreads();
    float base = (wid == 0) ? 0.f : wsum[wid - 1];
    Cs[tid] = base + s;
    float SQ = wsum[15];
    __syncthreads();

    // ---- binary search: m = #{Qs < -P}  (ties contribute 0 either side)
    float key = -P;
    int lo = 0, hi = N;
    #pragma unroll
    for (int it = 0; it < 9; it++) {
        int mid = (lo + hi) >> 1;
        bool lt = Qs[mid] < key;
        lo = lt ? mid + 1 : lo;
        hi = lt ? hi : mid;
    }
    float Cm = (lo == 0) ? 0.f : Cs[lo - 1];
    float T  = (float)(N - 2 * lo) * P + SQ - 2.f * Cm;

    float S = 0.55f * ((float)(N - 1) * P + SQ - Q)
            + 0.45f * (T - fabsf(P + Q));
    g_S[(b * N + tid) * HP + k] = S;
}

// ---------------------------------------------------------------------------
// kB: epilogue.  Grid = 128 x 512 thr (one wave); warp per (b,i) row.
// Batched S loads (MLP=4), then GEMV + shfl reduce + softplus combine.
// ---------------------------------------------------------------------------
__global__ __launch_bounds__(512) void kB(
    const float* __restrict__ inp, const float* __restrict__ W2,
    const float* __restrict__ b2, float* __restrict__ out)
{
    int w    = threadIdx.x >> 5;
    int lane = threadIdx.x & 31;
    int row  = blockIdx.x * 16 + w;         // b*N + i, 0..2047

    const float* Sr = g_S + row * HP;

    // batched loads first (4 outstanding), then compute
    float sv[4];
    #pragma unroll
    for (int cc = 0; cc < 4; cc++) {
        int kc = lane + 32 * cc;
        sv[cc] = (kc < HID) ? Sr[kc] : 0.f;
    }

    float par[OUTF];
    #pragma unroll
    for (int o = 0; o < OUTF; o++) par[o] = 0.f;

    #pragma unroll
    for (int cc = 0; cc < 4; cc++) {
        int kc = lane + 32 * cc;
        if (kc < HID) {
            #pragma unroll
            for (int o = 0; o < OUTF; o++)
                par[o] += sv[cc] * W2[kc * OUTF + o];
        }
    }
    #pragma unroll
    for (int off = 16; off > 0; off >>= 1)
        #pragma unroll
        for (int o = 0; o < OUTF; o++)
            par[o] += __shfl_down_sync(FULL, par[o], off);

    if (lane == 0) {
        const float* e = inp + row * 6;
        float* ot = out + row * 6;
        float p0 = par[0] + (float)(N - 1) * b2[0];
        float p1 = par[1] + (float)(N - 1) * b2[1];
        float p2 = par[2] + (float)(N - 1) * b2[2];
        float p3 = par[3] + (float)(N - 1) * b2[3];
        float p4 = par[4] + (float)(N - 1) * b2[4];
        float p5 = par[5] + (float)(N - 1) * b2[5];
        ot[0] = e[0] + 0.1f * p0;
        ot[1] = e[1] + 0.1f * p1;
        ot[2] = e[2] + 0.1f * p2;
        ot[3] = e[3] + 0.1f * p3;
        ot[4] = 0.1f * softplus_f(p4);
        ot[5] = 0.1f * softplus_f(p5);
    }
}

// ---------------------------------------------------------------------------
extern "C" void kernel_launch(void* const* d_in, const int* in_sizes, int n_in,
                              void* d_out, int out_size)
{
    const float* inp = (const float*)d_in[0];
    const float* W1  = (const float*)d_in[1];
    const float* b1  = (const float*)d_in[2];
    const float* W2  = (const float*)d_in[3];
    const float* b2  = (const float*)d_in[4];
    float* out = (float*)d_out;

    kA<<<B * HID, 512>>>(inp, W1, b1);
    kB<<<B * N / 16, 512>>>(inp, W2, b2, out);
}